// round 1
// baseline (speedup 1.0000x reference)
#include <cuda_runtime.h>
#include <math.h>

#define B_ 4
#define T_ 1024
#define E_ 256
#define V_ 32000
#define NTOK (B_*T_)

// Scratch (device globals; no allocation allowed)
__device__ float g_c[NTOK * 24];          // tanh(ln(...)) comp features
__device__ float g_states[NTOK * 576];    // flattened scan states
__device__ float g_h[NTOK * 512];         // gelu hidden

__device__ __forceinline__ float warp_sum(float v) {
#pragma unroll
    for (int o = 16; o > 0; o >>= 1) v += __shfl_xor_sync(0xffffffffu, v, o);
    return v;
}

// ---------------------------------------------------------------------------
// Kernel 1: per-token  x=emb[id]; a=tanh(ln(x@Wax^T+bax)); c=tanh(ln(a@Wc^T+bc))
// One block (384 threads = 12 warps) per token.
// ---------------------------------------------------------------------------
__global__ void token_kernel(const int* __restrict__ ids,
                             const float* __restrict__ emb,
                             const float* __restrict__ Wax, const float* __restrict__ bax,
                             const float* __restrict__ gax, const float* __restrict__ betax,
                             const float* __restrict__ Wc,  const float* __restrict__ bc,
                             const float* __restrict__ gc,  const float* __restrict__ betac)
{
    __shared__ float xsh[E_];
    __shared__ float ash[12];

    const int n   = blockIdx.x;
    const int tid = threadIdx.x;
    const int id  = ids[n];

    for (int e = tid; e < E_; e += 384) xsh[e] = emb[(size_t)id * E_ + e];
    __syncthreads();

    const int w = tid >> 5, lane = tid & 31;
    // 12 dot products of length 256: one warp each
    {
        const float* wr = Wax + w * E_;
        float p = 0.f;
#pragma unroll
        for (int e = lane; e < E_; e += 32) p += xsh[e] * wr[e];
        p = warp_sum(p);
        if (lane == 0) ash[w] = p + bax[w];
    }
    __syncthreads();

    if (w == 0) {
        // LN over 12 + tanh
        float v   = (lane < 12) ? ash[lane] : 0.f;
        float mu  = warp_sum(v) * (1.f / 12.f);
        float dv  = (lane < 12) ? (v - mu) : 0.f;
        float var = warp_sum(dv * dv) * (1.f / 12.f);
        float r   = rsqrtf(var + 1e-5f);
        if (lane < 12) ash[lane] = tanhf(dv * r * gax[lane] + betax[lane]);
        __syncwarp();

        // a @ Wc^T + bc  (24 outputs, 12-length dots)
        float cr = 0.f;
        if (lane < 24) {
            cr = bc[lane];
#pragma unroll
            for (int k = 0; k < 12; k++) cr += ash[k] * Wc[lane * 12 + k];
        }
        // LN over 24 + tanh
        float v2   = (lane < 24) ? cr : 0.f;
        float mu2  = warp_sum(v2) * (1.f / 24.f);
        float dv2  = (lane < 24) ? (cr - mu2) : 0.f;
        float var2 = warp_sum(dv2 * dv2) * (1.f / 24.f);
        float r2   = rsqrtf(var2 + 1e-5f);
        if (lane < 24) g_c[n * 24 + lane] = tanhf(dv2 * r2 * gc[lane] + betac[lane]);
    }
}

// ---------------------------------------------------------------------------
// Kernel 2: sequential decay scan. 1 block per batch, 576 threads = (i,j) pair.
//   s_t = d*s_{t-1} + m*c_t[i]*c_t[j]; write every state, and the final state.
// ---------------------------------------------------------------------------
__global__ void scan_kernel(const float* __restrict__ decay_p,
                            const float* __restrict__ mix_p,
                            float* __restrict__ final_out)
{
    __shared__ float csh[64 * 24];
    const int b = blockIdx.x, tid = threadIdx.x;
    const int i = tid / 24, j = tid % 24;

    const float d = 1.f / (1.f + expf(-decay_p[0]));
    const float m = 1.f / (1.f + expf(-mix_p[0]));

    float s = 0.f;
    for (int t0 = 0; t0 < T_; t0 += 64) {
        for (int idx = tid; idx < 64 * 24; idx += 576)
            csh[idx] = g_c[(b * T_ + t0) * 24 + idx];
        __syncthreads();
#pragma unroll 4
        for (int tt = 0; tt < 64; tt++) {
            s = d * s + m * csh[tt * 24 + i] * csh[tt * 24 + j];
            g_states[(size_t)(b * T_ + t0 + tt) * 576 + tid] = s;
        }
        __syncthreads();
    }
    final_out[b * 576 + tid] = s;
}

// ---------------------------------------------------------------------------
// Kernel 3/4: C[n,m] = act( sum_k A[n,k]*Bm[m,k] + bias[m] )
// A row-major [N,K], Bm row-major [M,K] (so this is A * B^T).
// 128x128 tile, BK=32, 256 threads, 8x8 per-thread micro-tile. K%32==0, tiles exact.
// ---------------------------------------------------------------------------
template <bool GELU>
__global__ void gemm_nt(const float* __restrict__ A, const float* __restrict__ Bm,
                        const float* __restrict__ bias, float* __restrict__ C,
                        int N, int M, int K)
{
    __shared__ float As[32][128];
    __shared__ float Bs[32][128];

    const int tid = threadIdx.x;
    const int n0  = blockIdx.y * 128;
    const int m0  = blockIdx.x * 128;
    const int tr  = (tid >> 4) * 8;   // row offset in tile
    const int tc  = (tid & 15) * 8;   // col offset in tile

    float acc[8][8];
#pragma unroll
    for (int r = 0; r < 8; r++)
#pragma unroll
        for (int c = 0; c < 8; c++) acc[r][c] = 0.f;

    for (int k0 = 0; k0 < K; k0 += 32) {
#pragma unroll
        for (int l = 0; l < 4; l++) {
            int lin = tid + l * 256;          // 0..1023 float4 slots
            int r   = lin >> 3;               // tile row 0..127
            int q   = lin & 7;                // float4 within the 32 k's
            float4 va = *(const float4*)(A  + (size_t)(n0 + r) * K + k0 + q * 4);
            As[q * 4 + 0][r] = va.x; As[q * 4 + 1][r] = va.y;
            As[q * 4 + 2][r] = va.z; As[q * 4 + 3][r] = va.w;
            float4 vb = *(const float4*)(Bm + (size_t)(m0 + r) * K + k0 + q * 4);
            Bs[q * 4 + 0][r] = vb.x; Bs[q * 4 + 1][r] = vb.y;
            Bs[q * 4 + 2][r] = vb.z; Bs[q * 4 + 3][r] = vb.w;
        }
        __syncthreads();

#pragma unroll
        for (int k = 0; k < 32; k++) {
            float ra[8], rb[8];
#pragma unroll
            for (int x = 0; x < 8; x++) { ra[x] = As[k][tr + x]; rb[x] = Bs[k][tc + x]; }
#pragma unroll
            for (int r = 0; r < 8; r++)
#pragma unroll
                for (int c = 0; c < 8; c++) acc[r][c] = fmaf(ra[r], rb[c], acc[r][c]);
        }
        __syncthreads();
    }

#pragma unroll
    for (int r = 0; r < 8; r++) {
        const int n = n0 + tr + r;
#pragma unroll
        for (int c = 0; c < 8; c++) {
            const int m = m0 + tc + c;
            float x = acc[r][c] + bias[m];
            if (GELU) x = 0.5f * x * (1.f + erff(x * 0.70710678118654752f));
            C[(size_t)n * M + m] = x;
        }
    }
}

// ---------------------------------------------------------------------------
extern "C" void kernel_launch(void* const* d_in, const int* in_sizes, int n_in,
                              void* d_out, int out_size)
{
    const int*   ids    = (const int*)  d_in[0];
    const float* emb    = (const float*)d_in[1];
    const float* Wax    = (const float*)d_in[2];
    const float* bax    = (const float*)d_in[3];
    const float* gax    = (const float*)d_in[4];
    const float* betax  = (const float*)d_in[5];
    const float* Wc     = (const float*)d_in[6];
    const float* bc     = (const float*)d_in[7];
    const float* gc     = (const float*)d_in[8];
    const float* betac  = (const float*)d_in[9];
    const float* decayp = (const float*)d_in[10];
    const float* mixp   = (const float*)d_in[11];
    const float* W1     = (const float*)d_in[12];
    const float* b1     = (const float*)d_in[13];
    const float* W2     = (const float*)d_in[14];
    const float* b2     = (const float*)d_in[15];

    float* out       = (float*)d_out;
    float* logits    = out;                               // [4096, 32000]
    float* final_out = out + (size_t)NTOK * V_;           // [4, 24, 24]

    float *states_p, *h_p;
    cudaGetSymbolAddress((void**)&states_p, g_states);
    cudaGetSymbolAddress((void**)&h_p, g_h);

    token_kernel<<<NTOK, 384>>>(ids, emb, Wax, bax, gax, betax, Wc, bc, gc, betac);
    scan_kernel<<<B_, 576>>>(decayp, mixp, final_out);

    dim3 g1(512 / 128, NTOK / 128);       // (4, 32)
    gemm_nt<true><<<g1, 256>>>(states_p, W1, b1, h_p, NTOK, 512, 576);

    dim3 g2(V_ / 128, NTOK / 128);        // (250, 32)
    gemm_nt<false><<<g2, 256>>>(h_p, W2, b2, logits, NTOK, V_, 512);
}

// round 3
// speedup vs baseline: 6.7255x; 6.7255x over previous
#include <cuda_runtime.h>
#include <cuda_fp16.h>
#include <math.h>
#include <stdint.h>

#define B_ 4
#define T_ 1024
#define E_ 256
#define V_ 32000
#define NTOK (B_*T_)
#define K1_ 576
#define H_  512

// ------------------------- device scratch (static; no allocs) --------------
__device__ float  g_c[NTOK * 24];
__device__ __half g_sH[NTOK * K1_];          // fp16 states
__device__ __half g_w1H[H_ * K1_];
__device__ __half g_hH[NTOK * H_];           // fp16 gelu hidden
__device__ __half g_w2H[(size_t)V_ * H_];

__device__ __forceinline__ float warp_sum(float v) {
#pragma unroll
    for (int o = 16; o > 0; o >>= 1) v += __shfl_xor_sync(0xffffffffu, v, o);
    return v;
}
__device__ __forceinline__ uint32_t smem_u32(const void* p) {
    uint32_t a;
    asm("{ .reg .u64 t; cvta.to.shared.u64 t, %1; cvt.u32.u64 %0, t; }" : "=r"(a) : "l"(p));
    return a;
}

// ---------------------------------------------------------------------------
// Kernel 1: per-token features
// ---------------------------------------------------------------------------
__global__ void token_kernel(const int* __restrict__ ids, const float* __restrict__ emb,
                             const float* __restrict__ Wax, const float* __restrict__ bax,
                             const float* __restrict__ gax, const float* __restrict__ betax,
                             const float* __restrict__ Wc,  const float* __restrict__ bc,
                             const float* __restrict__ gc,  const float* __restrict__ betac)
{
    __shared__ float xsh[E_];
    __shared__ float ash[12];
    const int n = blockIdx.x, tid = threadIdx.x;
    const int id = ids[n];
    for (int e = tid; e < E_; e += 384) xsh[e] = emb[(size_t)id * E_ + e];
    __syncthreads();
    const int w = tid >> 5, lane = tid & 31;
    {
        const float* wr = Wax + w * E_;
        float p = 0.f;
#pragma unroll
        for (int e = lane; e < E_; e += 32) p += xsh[e] * wr[e];
        p = warp_sum(p);
        if (lane == 0) ash[w] = p + bax[w];
    }
    __syncthreads();
    if (w == 0) {
        float v = (lane < 12) ? ash[lane] : 0.f;
        float mu = warp_sum(v) * (1.f / 12.f);
        float dv = (lane < 12) ? (v - mu) : 0.f;
        float var = warp_sum(dv * dv) * (1.f / 12.f);
        float r = rsqrtf(var + 1e-5f);
        if (lane < 12) ash[lane] = tanhf(dv * r * gax[lane] + betax[lane]);
        __syncwarp();
        float cr = 0.f;
        if (lane < 24) {
            cr = bc[lane];
#pragma unroll
            for (int k = 0; k < 12; k++) cr += ash[k] * Wc[lane * 12 + k];
        }
        float v2 = (lane < 24) ? cr : 0.f;
        float mu2 = warp_sum(v2) * (1.f / 24.f);
        float dv2 = (lane < 24) ? (cr - mu2) : 0.f;
        float var2 = warp_sum(dv2 * dv2) * (1.f / 24.f);
        float r2 = rsqrtf(var2 + 1e-5f);
        if (lane < 24) g_c[n * 24 + lane] = tanhf(dv2 * r2 * gc[lane] + betac[lane]);
    }
}

// ---------------------------------------------------------------------------
// Kernel 2: sequential decay scan -> fp16 states + fp32 final
// ---------------------------------------------------------------------------
__global__ void scan_kernel(const float* __restrict__ decay_p, const float* __restrict__ mix_p,
                            float* __restrict__ final_out)
{
    __shared__ float csh[64 * 24];
    const int b = blockIdx.x, tid = threadIdx.x;
    const int i = tid / 24, j = tid % 24;
    const float d = 1.f / (1.f + expf(-decay_p[0]));
    const float m = 1.f / (1.f + expf(-mix_p[0]));
    float s = 0.f;
    for (int t0 = 0; t0 < T_; t0 += 64) {
        for (int idx = tid; idx < 64 * 24; idx += 576)
            csh[idx] = g_c[(b * T_ + t0) * 24 + idx];
        __syncthreads();
#pragma unroll 4
        for (int tt = 0; tt < 64; tt++) {
            s = d * s + m * csh[tt * 24 + i] * csh[tt * 24 + j];
            g_sH[(size_t)(b * T_ + t0 + tt) * K1_ + tid] = __float2half_rn(s);
        }
        __syncthreads();
    }
    final_out[b * 576 + tid] = s;
}

// ---------------------------------------------------------------------------
// fp32 -> fp16 converter (by 4)
// ---------------------------------------------------------------------------
__global__ void tohalf4_kernel(const float* __restrict__ x, __half* __restrict__ y, int n4)
{
    int idx = blockIdx.x * blockDim.x + threadIdx.x;
    if (idx >= n4) return;
    float4 v = ((const float4*)x)[idx];
    __half2 a = __floats2half2_rn(v.x, v.y);
    __half2 b = __floats2half2_rn(v.z, v.w);
    ((__half2*)y)[idx * 2 + 0] = a;
    ((__half2*)y)[idx * 2 + 1] = b;
}

// ---------------------------------------------------------------------------
// mma.sync fp16 GEMM-NT:  OUT[r,c] = act( sum_k A[r,k]*B[c,k] + bias[c] )
// BM=128, BN=128, BK=32. 256 threads = 8 warps (2m x 4n), warp tile 64x32.
// Double-buffered cp.async. Padded smem rows (40 halves) -> conflict-free ldmatrix.
// ---------------------------------------------------------------------------
#define PAD_K 40
#define TILE_H (128 * PAD_K)           // halves per tile buffer
#define GEMM_SMEM_BYTES (4 * TILE_H * 2)  // 2 stages x (A+B) = 40960 B

template <bool GELU>
__global__ void __launch_bounds__(256, 2)
gemm_mma(const __half* __restrict__ A, const __half* __restrict__ Bm,
         const float* __restrict__ bias, float* __restrict__ outF,
         __half* __restrict__ outH, int N, int K)
{
    extern __shared__ __half sm[];
    const int tid  = threadIdx.x;
    const int wid  = tid >> 5, lane = tid & 31;
    const int wm   = wid >> 2;          // 0..1
    const int wn   = wid & 3;           // 0..3
    const int r0   = blockIdx.y * 128;
    const int c0   = blockIdx.x * 128;

    const uint32_t smb = smem_u32(sm);

    float acc[4][4][4];
#pragma unroll
    for (int i = 0; i < 4; i++)
#pragma unroll
        for (int j = 0; j < 4; j++)
#pragma unroll
            for (int q = 0; q < 4; q++) acc[i][j][q] = 0.f;

    const int NS = K / 32;

    // -------- async tile loader --------
    auto load_stage = [&](int ci, int st) {
        const int k0 = ci * 32;
        const uint32_t aBase = smb + (uint32_t)(st * 2 * TILE_H) * 2;
        const uint32_t bBase = aBase + (uint32_t)TILE_H * 2;
#pragma unroll
        for (int p = 0; p < 2; p++) {
            int idx = tid + p * 256;        // 0..511
            int row = idx >> 2;             // 0..127
            int c4  = idx & 3;              // 16B chunk
            const __half* gs = A + (size_t)(r0 + row) * K + k0 + c4 * 8;
            uint32_t sd = aBase + (uint32_t)(row * PAD_K + c4 * 8) * 2;
            asm volatile("cp.async.cg.shared.global [%0], [%1], 16;" :: "r"(sd), "l"(gs));
        }
#pragma unroll
        for (int p = 0; p < 2; p++) {
            int idx = tid + p * 256;
            int row = idx >> 2;
            int c4  = idx & 3;
            const __half* gs = Bm + (size_t)(c0 + row) * K + k0 + c4 * 8;
            uint32_t sd = bBase + (uint32_t)(row * PAD_K + c4 * 8) * 2;
            asm volatile("cp.async.cg.shared.global [%0], [%1], 16;" :: "r"(sd), "l"(gs));
        }
        asm volatile("cp.async.commit_group;" ::: "memory");
    };

    load_stage(0, 0);

    for (int ci = 0; ci < NS; ci++) {
        const int st = ci & 1;
        asm volatile("cp.async.wait_group 0;" ::: "memory");
        __syncthreads();
        if (ci + 1 < NS) load_stage(ci + 1, (ci + 1) & 1);

        const uint32_t aBase = smb + (uint32_t)(st * 2 * TILE_H) * 2;
        const uint32_t bBase = aBase + (uint32_t)TILE_H * 2;

#pragma unroll
        for (int kk = 0; kk < 2; kk++) {
            const int kb = kk * 16;
            uint32_t afr[4][4];
            uint32_t bfr[4][2];
#pragma unroll
            for (int mt = 0; mt < 4; mt++) {
                uint32_t addr = aBase +
                    (uint32_t)((wm * 64 + mt * 16 + (lane & 15)) * PAD_K + kb + (lane >> 4) * 8) * 2;
                asm volatile("ldmatrix.sync.aligned.m8n8.x4.shared.b16 {%0,%1,%2,%3}, [%4];"
                             : "=r"(afr[mt][0]), "=r"(afr[mt][1]), "=r"(afr[mt][2]), "=r"(afr[mt][3])
                             : "r"(addr));
            }
#pragma unroll
            for (int nt = 0; nt < 4; nt++) {
                uint32_t addr = bBase +
                    (uint32_t)((wn * 32 + nt * 8 + (lane & 7)) * PAD_K + kb + ((lane >> 3) & 1) * 8) * 2;
                asm volatile("ldmatrix.sync.aligned.m8n8.x2.shared.b16 {%0,%1}, [%2];"
                             : "=r"(bfr[nt][0]), "=r"(bfr[nt][1]) : "r"(addr));
            }
#pragma unroll
            for (int mt = 0; mt < 4; mt++)
#pragma unroll
                for (int nt = 0; nt < 4; nt++) {
                    asm volatile(
                        "mma.sync.aligned.m16n8k16.row.col.f32.f16.f16.f32 "
                        "{%0,%1,%2,%3}, {%4,%5,%6,%7}, {%8,%9}, {%0,%1,%2,%3};"
                        : "+f"(acc[mt][nt][0]), "+f"(acc[mt][nt][1]),
                          "+f"(acc[mt][nt][2]), "+f"(acc[mt][nt][3])
                        : "r"(afr[mt][0]), "r"(afr[mt][1]), "r"(afr[mt][2]), "r"(afr[mt][3]),
                          "r"(bfr[nt][0]), "r"(bfr[nt][1]));
                }
        }
        __syncthreads();
    }

    // -------- epilogue --------
    const int g  = lane >> 2;     // 0..7
    const int tg = lane & 3;      // 0..3
#pragma unroll
    for (int nt = 0; nt < 4; nt++) {
        const int col = c0 + wn * 32 + nt * 8 + tg * 2;
        const float bi0 = __ldg(bias + col);
        const float bi1 = __ldg(bias + col + 1);
#pragma unroll
        for (int mt = 0; mt < 4; mt++) {
            const int row = r0 + wm * 64 + mt * 16 + g;
            float x0 = acc[mt][nt][0] + bi0;
            float x1 = acc[mt][nt][1] + bi1;
            float x2 = acc[mt][nt][2] + bi0;
            float x3 = acc[mt][nt][3] + bi1;
            if (GELU) {
                x0 = 0.5f * x0 * (1.f + erff(x0 * 0.70710678118654752f));
                x1 = 0.5f * x1 * (1.f + erff(x1 * 0.70710678118654752f));
                x2 = 0.5f * x2 * (1.f + erff(x2 * 0.70710678118654752f));
                x3 = 0.5f * x3 * (1.f + erff(x3 * 0.70710678118654752f));
                *(__half2*)(outH + (size_t)row * N + col)       = __floats2half2_rn(x0, x1);
                *(__half2*)(outH + (size_t)(row + 8) * N + col) = __floats2half2_rn(x2, x3);
            } else {
                *(float2*)(outF + (size_t)row * N + col)       = make_float2(x0, x1);
                *(float2*)(outF + (size_t)(row + 8) * N + col) = make_float2(x2, x3);
            }
        }
    }
}

// ---------------------------------------------------------------------------
extern "C" void kernel_launch(void* const* d_in, const int* in_sizes, int n_in,
                              void* d_out, int out_size)
{
    const int*   ids    = (const int*)  d_in[0];
    const float* emb    = (const float*)d_in[1];
    const float* Wax    = (const float*)d_in[2];
    const float* bax    = (const float*)d_in[3];
    const float* gax    = (const float*)d_in[4];
    const float* betax  = (const float*)d_in[5];
    const float* Wc     = (const float*)d_in[6];
    const float* bc     = (const float*)d_in[7];
    const float* gc     = (const float*)d_in[8];
    const float* betac  = (const float*)d_in[9];
    const float* decayp = (const float*)d_in[10];
    const float* mixp   = (const float*)d_in[11];
    const float* W1     = (const float*)d_in[12];
    const float* b1     = (const float*)d_in[13];
    const float* W2     = (const float*)d_in[14];
    const float* b2     = (const float*)d_in[15];

    float* out       = (float*)d_out;
    float* logits    = out;
    float* final_out = out + (size_t)NTOK * V_;

    __half *sH, *w1H, *hH, *w2H;
    cudaGetSymbolAddress((void**)&sH,  g_sH);
    cudaGetSymbolAddress((void**)&w1H, g_w1H);
    cudaGetSymbolAddress((void**)&hH,  g_hH);
    cudaGetSymbolAddress((void**)&w2H, g_w2H);

    token_kernel<<<NTOK, 384>>>(ids, emb, Wax, bax, gax, betax, Wc, bc, gc, betac);
    scan_kernel<<<B_, 576>>>(decayp, mixp, final_out);

    tohalf4_kernel<<<(H_ * K1_ / 4 + 255) / 256, 256>>>(W1, w1H, H_ * K1_ / 4);
    tohalf4_kernel<<<((int)((size_t)V_ * H_ / 4) + 255) / 256, 256>>>(W2, w2H, (int)((size_t)V_ * H_ / 4));

    // GEMM1: h = gelu(states @ W1^T + b1)  [4096 x 512], K=576 -> fp16
    {
        dim3 g(H_ / 128, NTOK / 128);   // (4, 32)
        gemm_mma<true><<<g, 256, GEMM_SMEM_BYTES>>>(sH, w1H, b1, nullptr, hH, H_, K1_);
    }
    // GEMM2: logits = h @ W2^T + b2  [4096 x 32000], K=512 -> fp32
    {
        dim3 g(V_ / 128, NTOK / 128);   // (250, 32)
        gemm_mma<false><<<g, 256, GEMM_SMEM_BYTES>>>(hH, w2H, b2, logits, nullptr, V_, H_);
    }
}

// round 4
// speedup vs baseline: 7.2226x; 1.0739x over previous
#include <cuda_runtime.h>
#include <cuda_fp16.h>
#include <math.h>
#include <stdint.h>

#define B_ 4
#define T_ 1024
#define E_ 256
#define V_ 32000
#define NTOK (B_*T_)
#define K1_ 576
#define H_  512

// ------------------------- device scratch (static; no allocs) --------------
__device__ float  g_c[NTOK * 24];
__device__ __half g_sH[NTOK * K1_];          // fp16 states
__device__ __half g_w1H[H_ * K1_];
__device__ __half g_hH[NTOK * H_];           // fp16 gelu hidden
__device__ __half g_w2H[(size_t)V_ * H_];

__device__ __forceinline__ float warp_sum(float v) {
#pragma unroll
    for (int o = 16; o > 0; o >>= 1) v += __shfl_xor_sync(0xffffffffu, v, o);
    return v;
}
__device__ __forceinline__ uint32_t smem_u32(const void* p) {
    uint32_t a;
    asm("{ .reg .u64 t; cvta.to.shared.u64 t, %1; cvt.u32.u64 %0, t; }" : "=r"(a) : "l"(p));
    return a;
}

// ---------------------------------------------------------------------------
// Kernel 1: per-token features
// ---------------------------------------------------------------------------
__global__ void token_kernel(const int* __restrict__ ids, const float* __restrict__ emb,
                             const float* __restrict__ Wax, const float* __restrict__ bax,
                             const float* __restrict__ gax, const float* __restrict__ betax,
                             const float* __restrict__ Wc,  const float* __restrict__ bc,
                             const float* __restrict__ gc,  const float* __restrict__ betac)
{
    __shared__ float xsh[E_];
    __shared__ float ash[12];
    const int n = blockIdx.x, tid = threadIdx.x;
    const int id = ids[n];
    for (int e = tid; e < E_; e += 384) xsh[e] = emb[(size_t)id * E_ + e];
    __syncthreads();
    const int w = tid >> 5, lane = tid & 31;
    {
        const float* wr = Wax + w * E_;
        float p = 0.f;
#pragma unroll
        for (int e = lane; e < E_; e += 32) p += xsh[e] * wr[e];
        p = warp_sum(p);
        if (lane == 0) ash[w] = p + bax[w];
    }
    __syncthreads();
    if (w == 0) {
        float v = (lane < 12) ? ash[lane] : 0.f;
        float mu = warp_sum(v) * (1.f / 12.f);
        float dv = (lane < 12) ? (v - mu) : 0.f;
        float var = warp_sum(dv * dv) * (1.f / 12.f);
        float r = rsqrtf(var + 1e-5f);
        if (lane < 12) ash[lane] = tanhf(dv * r * gax[lane] + betax[lane]);
        __syncwarp();
        float cr = 0.f;
        if (lane < 24) {
            cr = bc[lane];
#pragma unroll
            for (int k = 0; k < 12; k++) cr += ash[k] * Wc[lane * 12 + k];
        }
        float v2 = (lane < 24) ? cr : 0.f;
        float mu2 = warp_sum(v2) * (1.f / 24.f);
        float dv2 = (lane < 24) ? (cr - mu2) : 0.f;
        float var2 = warp_sum(dv2 * dv2) * (1.f / 24.f);
        float r2 = rsqrtf(var2 + 1e-5f);
        if (lane < 24) g_c[n * 24 + lane] = tanhf(dv2 * r2 * gc[lane] + betac[lane]);
    }
}

// ---------------------------------------------------------------------------
// Kernel 2: sequential decay scan -> fp16 states + fp32 final
// ---------------------------------------------------------------------------
__global__ void scan_kernel(const float* __restrict__ decay_p, const float* __restrict__ mix_p,
                            float* __restrict__ final_out)
{
    __shared__ float csh[64 * 24];
    const int b = blockIdx.x, tid = threadIdx.x;
    const int i = tid / 24, j = tid % 24;
    const float d = 1.f / (1.f + expf(-decay_p[0]));
    const float m = 1.f / (1.f + expf(-mix_p[0]));
    float s = 0.f;
    for (int t0 = 0; t0 < T_; t0 += 64) {
        for (int idx = tid; idx < 64 * 24; idx += 576)
            csh[idx] = g_c[(b * T_ + t0) * 24 + idx];
        __syncthreads();
#pragma unroll 4
        for (int tt = 0; tt < 64; tt++) {
            s = d * s + m * csh[tt * 24 + i] * csh[tt * 24 + j];
            g_sH[(size_t)(b * T_ + t0 + tt) * K1_ + tid] = __float2half_rn(s);
        }
        __syncthreads();
    }
    final_out[b * 576 + tid] = s;
}

// ---------------------------------------------------------------------------
// fp32 -> fp16 converter (by 4)
// ---------------------------------------------------------------------------
__global__ void tohalf4_kernel(const float* __restrict__ x, __half* __restrict__ y, int n4)
{
    int idx = blockIdx.x * blockDim.x + threadIdx.x;
    if (idx >= n4) return;
    float4 v = ((const float4*)x)[idx];
    __half2 a = __floats2half2_rn(v.x, v.y);
    __half2 b = __floats2half2_rn(v.z, v.w);
    ((__half2*)y)[idx * 2 + 0] = a;
    ((__half2*)y)[idx * 2 + 1] = b;
}

// ---------------------------------------------------------------------------
// mma.sync fp16 GEMM-NT:  OUT[r,c] = act( sum_k A[r,k]*B[c,k] + bias[c] )
// BM=128, BN=128, BK=32. 256 threads = 8 warps (2m x 4n), warp tile 64x32.
// 3-stage cp.async pipeline, wait_group 1, single barrier per K-chunk.
// Padded smem rows (40 halves) -> conflict-free ldmatrix.
// ---------------------------------------------------------------------------
#define PAD_K 40
#define TILE_H (128 * PAD_K)               // halves per (A or B) tile buffer
#define STAGE_H (2 * TILE_H)               // halves per stage (A + B)
#define NSTAGE 3
#define GEMM_SMEM_BYTES (NSTAGE * STAGE_H * 2)   // 61440 B

template <bool GELU>
__global__ void __launch_bounds__(256, 2)
gemm_mma(const __half* __restrict__ A, const __half* __restrict__ Bm,
         const float* __restrict__ bias, float* __restrict__ outF,
         __half* __restrict__ outH, int N, int K)
{
    extern __shared__ __half sm[];
    const int tid  = threadIdx.x;
    const int wid  = tid >> 5, lane = tid & 31;
    const int wm   = wid >> 2;          // 0..1
    const int wn   = wid & 3;           // 0..3
    const int r0   = blockIdx.y * 128;
    const int c0   = blockIdx.x * 128;

    const uint32_t smb = smem_u32(sm);

    float acc[4][4][4];
#pragma unroll
    for (int i = 0; i < 4; i++)
#pragma unroll
        for (int j = 0; j < 4; j++)
#pragma unroll
            for (int q = 0; q < 4; q++) acc[i][j][q] = 0.f;

    const int NS = K / 32;

    // -------- async tile loader (one K-chunk into stage st) --------
    auto load_stage = [&](int ci, int st) {
        const int k0 = ci * 32;
        const uint32_t aBase = smb + (uint32_t)(st * STAGE_H) * 2;
        const uint32_t bBase = aBase + (uint32_t)TILE_H * 2;
#pragma unroll
        for (int p = 0; p < 2; p++) {
            int idx = tid + p * 256;        // 0..511
            int row = idx >> 2;             // 0..127
            int c4  = idx & 3;              // 16B chunk
            const __half* gs = A + (size_t)(r0 + row) * K + k0 + c4 * 8;
            uint32_t sd = aBase + (uint32_t)(row * PAD_K + c4 * 8) * 2;
            asm volatile("cp.async.cg.shared.global [%0], [%1], 16;" :: "r"(sd), "l"(gs));
        }
#pragma unroll
        for (int p = 0; p < 2; p++) {
            int idx = tid + p * 256;
            int row = idx >> 2;
            int c4  = idx & 3;
            const __half* gs = Bm + (size_t)(c0 + row) * K + k0 + c4 * 8;
            uint32_t sd = bBase + (uint32_t)(row * PAD_K + c4 * 8) * 2;
            asm volatile("cp.async.cg.shared.global [%0], [%1], 16;" :: "r"(sd), "l"(gs));
        }
        asm volatile("cp.async.commit_group;" ::: "memory");
    };

    // prologue: two stages in flight
    load_stage(0, 0);
    load_stage(1, 1);

    for (int ci = 0; ci < NS; ci++) {
        const int st = ci % NSTAGE;
        // stage ci guaranteed complete while up to one newer group still flies
        if (ci == NS - 1) asm volatile("cp.async.wait_group 0;" ::: "memory");
        else              asm volatile("cp.async.wait_group 1;" ::: "memory");
        __syncthreads();
        if (ci + 2 < NS) load_stage(ci + 2, (ci + 2) % NSTAGE);

        const uint32_t aBase = smb + (uint32_t)(st * STAGE_H) * 2;
        const uint32_t bBase = aBase + (uint32_t)TILE_H * 2;

#pragma unroll
        for (int kk = 0; kk < 2; kk++) {
            const int kb = kk * 16;
            uint32_t afr[4][4];
            uint32_t bfr[4][2];
#pragma unroll
            for (int mt = 0; mt < 4; mt++) {
                uint32_t addr = aBase +
                    (uint32_t)((wm * 64 + mt * 16 + (lane & 15)) * PAD_K + kb + (lane >> 4) * 8) * 2;
                asm volatile("ldmatrix.sync.aligned.m8n8.x4.shared.b16 {%0,%1,%2,%3}, [%4];"
                             : "=r"(afr[mt][0]), "=r"(afr[mt][1]), "=r"(afr[mt][2]), "=r"(afr[mt][3])
                             : "r"(addr));
            }
            // B fragments: one x4 ldmatrix covers two n-tiles (16 rows x k16)
#pragma unroll
            for (int ntp = 0; ntp < 2; ntp++) {
                uint32_t row = wn * 32 + ntp * 16 + ((lane >> 4) & 1) * 8 + (lane & 7);
                uint32_t kof = kb + ((lane >> 3) & 1) * 8;
                uint32_t addr = bBase + (uint32_t)(row * PAD_K + kof) * 2;
                asm volatile("ldmatrix.sync.aligned.m8n8.x4.shared.b16 {%0,%1,%2,%3}, [%4];"
                             : "=r"(bfr[ntp * 2][0]),     "=r"(bfr[ntp * 2][1]),
                               "=r"(bfr[ntp * 2 + 1][0]), "=r"(bfr[ntp * 2 + 1][1])
                             : "r"(addr));
            }
#pragma unroll
            for (int mt = 0; mt < 4; mt++)
#pragma unroll
                for (int nt = 0; nt < 4; nt++) {
                    asm volatile(
                        "mma.sync.aligned.m16n8k16.row.col.f32.f16.f16.f32 "
                        "{%0,%1,%2,%3}, {%4,%5,%6,%7}, {%8,%9}, {%0,%1,%2,%3};"
                        : "+f"(acc[mt][nt][0]), "+f"(acc[mt][nt][1]),
                          "+f"(acc[mt][nt][2]), "+f"(acc[mt][nt][3])
                        : "r"(afr[mt][0]), "r"(afr[mt][1]), "r"(afr[mt][2]), "r"(afr[mt][3]),
                          "r"(bfr[nt][0]), "r"(bfr[nt][1]));
                }
        }
    }

    // -------- epilogue --------
    const int g  = lane >> 2;     // 0..7
    const int tg = lane & 3;      // 0..3
#pragma unroll
    for (int nt = 0; nt < 4; nt++) {
        const int col = c0 + wn * 32 + nt * 8 + tg * 2;
        const float bi0 = __ldg(bias + col);
        const float bi1 = __ldg(bias + col + 1);
#pragma unroll
        for (int mt = 0; mt < 4; mt++) {
            const int row = r0 + wm * 64 + mt * 16 + g;
            float x0 = acc[mt][nt][0] + bi0;
            float x1 = acc[mt][nt][1] + bi1;
            float x2 = acc[mt][nt][2] + bi0;
            float x3 = acc[mt][nt][3] + bi1;
            if (GELU) {
                x0 = 0.5f * x0 * (1.f + erff(x0 * 0.70710678118654752f));
                x1 = 0.5f * x1 * (1.f + erff(x1 * 0.70710678118654752f));
                x2 = 0.5f * x2 * (1.f + erff(x2 * 0.70710678118654752f));
                x3 = 0.5f * x3 * (1.f + erff(x3 * 0.70710678118654752f));
                *(__half2*)(outH + (size_t)row * N + col)       = __floats2half2_rn(x0, x1);
                *(__half2*)(outH + (size_t)(row + 8) * N + col) = __floats2half2_rn(x2, x3);
            } else {
                *(float2*)(outF + (size_t)row * N + col)       = make_float2(x0, x1);
                *(float2*)(outF + (size_t)(row + 8) * N + col) = make_float2(x2, x3);
            }
        }
    }
}

// ---------------------------------------------------------------------------
extern "C" void kernel_launch(void* const* d_in, const int* in_sizes, int n_in,
                              void* d_out, int out_size)
{
    const int*   ids    = (const int*)  d_in[0];
    const float* emb    = (const float*)d_in[1];
    const float* Wax    = (const float*)d_in[2];
    const float* bax    = (const float*)d_in[3];
    const float* gax    = (const float*)d_in[4];
    const float* betax  = (const float*)d_in[5];
    const float* Wc     = (const float*)d_in[6];
    const float* bc     = (const float*)d_in[7];
    const float* gc     = (const float*)d_in[8];
    const float* betac  = (const float*)d_in[9];
    const float* decayp = (const float*)d_in[10];
    const float* mixp   = (const float*)d_in[11];
    const float* W1     = (const float*)d_in[12];
    const float* b1     = (const float*)d_in[13];
    const float* W2     = (const float*)d_in[14];
    const float* b2     = (const float*)d_in[15];

    float* out       = (float*)d_out;
    float* logits    = out;
    float* final_out = out + (size_t)NTOK * V_;

    __half *sH, *w1H, *hH, *w2H;
    cudaGetSymbolAddress((void**)&sH,  g_sH);
    cudaGetSymbolAddress((void**)&w1H, g_w1H);
    cudaGetSymbolAddress((void**)&hH,  g_hH);
    cudaGetSymbolAddress((void**)&w2H, g_w2H);

    cudaFuncSetAttribute(gemm_mma<true>,  cudaFuncAttributeMaxDynamicSharedMemorySize, GEMM_SMEM_BYTES);
    cudaFuncSetAttribute(gemm_mma<false>, cudaFuncAttributeMaxDynamicSharedMemorySize, GEMM_SMEM_BYTES);

    token_kernel<<<NTOK, 384>>>(ids, emb, Wax, bax, gax, betax, Wc, bc, gc, betac);
    scan_kernel<<<B_, 576>>>(decayp, mixp, final_out);

    tohalf4_kernel<<<(H_ * K1_ / 4 + 255) / 256, 256>>>(W1, w1H, H_ * K1_ / 4);
    tohalf4_kernel<<<((int)((size_t)V_ * H_ / 4) + 255) / 256, 256>>>(W2, w2H, (int)((size_t)V_ * H_ / 4));

    // GEMM1: h = gelu(states @ W1^T + b1)  [4096 x 512], K=576 -> fp16
    {
        dim3 g(H_ / 128, NTOK / 128);   // (4, 32)
        gemm_mma<true><<<g, 256, GEMM_SMEM_BYTES>>>(sH, w1H, b1, nullptr, hH, H_, K1_);
    }
    // GEMM2: logits = h @ W2^T + b2  [4096 x 32000], K=512 -> fp32
    {
        dim3 g(V_ / 128, NTOK / 128);   // (250, 32)
        gemm_mma<false><<<g, 256, GEMM_SMEM_BYTES>>>(hH, w2H, b2, logits, nullptr, V_, H_);
    }
}